// round 9
// baseline (speedup 1.0000x reference)
#include <cuda_runtime.h>

#define Bn   4
#define Cn   256
#define Hf   64
#define Wf   64
#define HW   (Hf*Wf)
#define COMPn 64
#define OH   128
#define OW   128
#define EPSc 1e-5f
#define TPAD 28

typedef unsigned long long u64t;

#define FMA2(d, a, b, c) asm("fma.rn.f32x2 %0, %1, %2, %3;" : "=l"(d) : "l"(a), "l"(b), "l"(c))
#define ADD2(d, a, b)    asm("add.rn.f32x2 %0, %1, %2;"     : "=l"(d) : "l"(a), "l"(b))

__device__ __forceinline__ u64t dup2(float v) {
    u64t r; asm("mov.b64 %0, {%1, %1};" : "=l"(r) : "f"(v)); return r;
}
__device__ __forceinline__ float2 unpk(u64t v) {
    float lo, hi; asm("mov.b64 {%0, %1}, %2;" : "=f"(lo), "=f"(hi) : "l"(v));
    return make_float2(lo, hi);
}
__device__ __forceinline__ u64t pack2(float a, float b) {
    u64t r; asm("mov.b64 %0, {%1, %2};" : "=l"(r) : "f"(a), "f"(b)); return r;
}

__device__ float g_act[Bn*COMPn*HW];
// masks q-major: [b][q][tileY*8+tileX][pixInTile(64)][28]
__device__ float g_mask3[Bn*4*64*64*28];

// ---------------------------------------------------------------------------
// K1: unchanged (27 us).
// ---------------------------------------------------------------------------
__global__ __launch_bounds__(256) void k1_comp_bn_silu(
    const float* __restrict__ x, const float* __restrict__ w_comp,
    const float* __restrict__ gamma, const float* __restrict__ beta,
    const float* __restrict__ mean, const float* __restrict__ var)
{
    __shared__ __align__(16) float sw[8*256*2];
    __shared__ __align__(16) u64t red[128][2][4][2];

    const int tid     = threadIdx.x;
    const int h       = tid >> 7;
    const int ht      = tid & 127;
    const int b       = blockIdx.x >> 3;
    const int pixBase = (blockIdx.x & 7) << 9;
    const int oBase   = blockIdx.y << 3;

    for (int i = tid; i < 8*256; i += 256) {
        int o = i >> 8, c = i & 255;
        float w = w_comp[(oBase + o)*256 + c];
        sw[2*i] = w; sw[2*i+1] = w;
    }
    __syncthreads();

    const int pix0 = pixBase + 4*ht;
    const float* xb = x + (size_t)b*Cn*HW + (size_t)(h*128)*HW + pix0;

    u64t acc[8][2];
    #pragma unroll
    for (int o = 0; o < 8; o++) { acc[o][0] = 0ULL; acc[o][1] = 0ULL; }

    const ulonglong2* sw2 = reinterpret_cast<const ulonglong2*>(sw);
    const int c4Base = h*32;

    ulonglong2 buf[2][4];
    #define LD4(s, g) { const float* _p = xb + (size_t)(g)*4*HW; \
        buf[s][0] = *(const ulonglong2*)(_p); \
        buf[s][1] = *(const ulonglong2*)(_p + HW); \
        buf[s][2] = *(const ulonglong2*)(_p + 2*HW); \
        buf[s][3] = *(const ulonglong2*)(_p + 3*HW); }
    #define K1STEP(s, g) { const int _gc = c4Base + (g); \
        _Pragma("unroll") for (int o = 0; o < 8; o++) { \
            ulonglong2 wA = sw2[o*128 + _gc*2]; \
            ulonglong2 wB = sw2[o*128 + _gc*2 + 1]; \
            FMA2(acc[o][0], wA.x, buf[s][0].x, acc[o][0]); \
            FMA2(acc[o][1], wA.x, buf[s][0].y, acc[o][1]); \
            FMA2(acc[o][0], wA.y, buf[s][1].x, acc[o][0]); \
            FMA2(acc[o][1], wA.y, buf[s][1].y, acc[o][1]); \
            FMA2(acc[o][0], wB.x, buf[s][2].x, acc[o][0]); \
            FMA2(acc[o][1], wB.x, buf[s][2].y, acc[o][1]); \
            FMA2(acc[o][0], wB.y, buf[s][3].x, acc[o][0]); \
            FMA2(acc[o][1], wB.y, buf[s][3].y, acc[o][1]); } }

    LD4(0, 0); LD4(1, 1);
    #pragma unroll 1
    for (int g = 0; g < 32; g += 2) {
        K1STEP(0, g);     if (g + 2 < 32) LD4(0, g + 2);
        K1STEP(1, g + 1); if (g + 3 < 32) LD4(1, g + 3);
    }
    #undef LD4
    #undef K1STEP

    #pragma unroll
    for (int j = 0; j < 4; j++) {
        red[ht][1 ^ h][j][0] = acc[(1 ^ h)*4 + j][0];
        red[ht][1 ^ h][j][1] = acc[(1 ^ h)*4 + j][1];
    }
    __syncthreads();

    #pragma unroll
    for (int j = 0; j < 4; j++) {
        int og = oBase + h*4 + j;
        u64t a0 = acc[h*4 + j][0], a1 = acc[h*4 + j][1];
        ADD2(a0, a0, red[ht][h][j][0]);
        ADD2(a1, a1, red[ht][h][j][1]);
        float inv = gamma[og] * rsqrtf(var[og] + EPSc);
        float mu = mean[og], bt = beta[og];
        float2 p0 = unpk(a0), p1 = unpk(a1);
        float v0 = (p0.x - mu)*inv + bt;
        float v1 = (p0.y - mu)*inv + bt;
        float v2 = (p1.x - mu)*inv + bt;
        float v3 = (p1.y - mu)*inv + bt;
        v0 = v0 / (1.f + __expf(-v0));
        v1 = v1 / (1.f + __expf(-v1));
        v2 = v2 / (1.f + __expf(-v2));
        v3 = v3 / (1.f + __expf(-v3));
        *reinterpret_cast<float4*>(&g_act[((size_t)b*COMPn + og)*HW + pix0]) =
            make_float4(v0, v1, v2, v3);
    }
}

// ---------------------------------------------------------------------------
// K2: 3x3 encoder conv + softmax. Fine-grained: 8x8 px tile, 64 thr,
// grid (8,8,16) = 1024 blocks (~7 blocks/SM -> balanced fma-pipe load).
// 1 px/thread, 13 packed accs. Weights staged once (63KB, division-free),
// acts double-buffered in 4-ch chunks. smem ~68KB (3 CTAs/SM).
// ---------------------------------------------------------------------------
#define K2APCH 110           // 10 rows x 11 cols per channel
#define K2_BUF (4*K2APCH)

__global__ __launch_bounds__(64) void k2_conv_softmax(const float* __restrict__ w_enc)
{
    extern __shared__ __align__(16) float smem[];
    float* s_w   = smem;                 // 64*9*TPAD = 16128 floats
    float* s_act = smem + 64*9*TPAD;     // 2 x 440 floats

    const int tid  = threadIdx.x;
    const int trow = tid >> 3, tcol = tid & 7;
    const int bz   = blockIdx.z;
    const int b    = bz >> 2;
    const int q    = bz & 3;
    const int row0 = blockIdx.y * 8, col0 = blockIdx.x * 8;

    const float* actb = g_act + (size_t)b*COMPn*HW;

    // hoisted staging offsets: 7 slots covering 440 elements (soff == idx)
    int  goff[7];
    bool pred[7];
    bool inr[7];
    #pragma unroll
    for (int i = 0; i < 7; i++) {
        int idx = tid + i*64;
        int cl = idx / 110, r = idx - cl*110;
        int ly = r / 11, lx = r - ly*11;
        int gy = row0 - 1 + ly, gx = col0 - 1 + lx;
        inr[i]  = (idx < 440);
        pred[i] = inr[i] && ((unsigned)gy < Hf) && ((unsigned)gx < Wf);
        goff[i] = cl*HW + gy*Wf + gx;
    }

    float pre[7];
    #define K2_LDG(chunk) { const float* _a = actb + (size_t)(chunk)*4*HW; \
        _Pragma("unroll") for (int i = 0; i < 7; i++) \
            pre[i] = pred[i] ? _a[goff[i]] : 0.f; }
    #define K2_STS(buf) { float* _d = s_act + (buf)*K2_BUF; \
        _Pragma("unroll") for (int i = 0; i < 7; i++) \
            if (inr[i]) _d[tid + i*64] = pre[i]; }

    K2_LDG(0);

    // weight staging, division-free: s_w[cj*TPAD + t] = w_enc[(t*4+q)*576 + cj]
    for (int i = tid; i < 576; i += 64) {
        s_w[i*TPAD + 25] = 0.f; s_w[i*TPAD + 26] = 0.f; s_w[i*TPAD + 27] = 0.f;
    }
    #pragma unroll 1
    for (int t = 0; t < 25; t++) {
        const float* wsrc = w_enc + (t*4 + q)*576;
        #pragma unroll
        for (int i = 0; i < 9; i++)
            s_w[(tid + i*64)*TPAD + t] = wsrc[tid + i*64];
    }

    K2_STS(0);
    __syncthreads();

    u64t acc[13];
    #pragma unroll
    for (int i = 0; i < 13; i++) acc[i] = 0ULL;

    #pragma unroll 1
    for (int ch = 0; ch < 16; ch++) {
        if (ch < 15) K2_LDG(ch + 1);

        const float* abuf = s_act + (ch & 1)*K2_BUF;
        #pragma unroll 1
        for (int cl = 0; cl < 4; cl++) {
            const int c = ch*4 + cl;
            const float* ab = abuf + cl*K2APCH + trow*11 + tcol;
            u64t ad[9];
            #pragma unroll
            for (int jy = 0; jy < 3; jy++)
                #pragma unroll
                for (int jx = 0; jx < 3; jx++)
                    ad[jy*3+jx] = dup2(ab[jy*11 + jx]);

            const float* wb = s_w + c*9*TPAD;
            #pragma unroll
            for (int j = 0; j < 9; j++) {
                const float* wj = wb + j*TPAD;
                const ulonglong2* w2 = reinterpret_cast<const ulonglong2*>(wj);
                ulonglong2 wA = w2[0], wB = w2[1], wC = w2[2];
                ulonglong2 wD = w2[3], wE = w2[4], wF = w2[5];
                u64t wG = *reinterpret_cast<const u64t*>(wj + 24);
                u64t a0 = ad[j];
                FMA2(acc[0],  wA.x, a0, acc[0]);
                FMA2(acc[1],  wA.y, a0, acc[1]);
                FMA2(acc[2],  wB.x, a0, acc[2]);
                FMA2(acc[3],  wB.y, a0, acc[3]);
                FMA2(acc[4],  wC.x, a0, acc[4]);
                FMA2(acc[5],  wC.y, a0, acc[5]);
                FMA2(acc[6],  wD.x, a0, acc[6]);
                FMA2(acc[7],  wD.y, a0, acc[7]);
                FMA2(acc[8],  wE.x, a0, acc[8]);
                FMA2(acc[9],  wE.y, a0, acc[9]);
                FMA2(acc[10], wF.x, a0, acc[10]);
                FMA2(acc[11], wF.y, a0, acc[11]);
                FMA2(acc[12], wG,   a0, acc[12]);
            }
        }

        if (ch < 15) K2_STS((ch + 1) & 1);
        __syncthreads();
    }
    #undef K2_LDG
    #undef K2_STS

    // softmax over t, store q-major with STG.128
    float v[28];
    #pragma unroll
    for (int i = 0; i < 13; i++) {
        float2 u = unpk(acc[i]);
        v[2*i] = u.x; v[2*i+1] = u.y;
    }
    float mx = v[0];
    #pragma unroll
    for (int t = 1; t < 25; t++) mx = fmaxf(mx, v[t]);
    float sum = 0.f;
    #pragma unroll
    for (int t = 0; t < 25; t++) { v[t] = __expf(v[t] - mx); sum += v[t]; }
    float r = 1.f / sum;
    #pragma unroll
    for (int t = 0; t < 25; t++) v[t] *= r;
    v[25] = 0.f; v[26] = 0.f; v[27] = 0.f;

    float* mp = g_mask3 +
        ((size_t)(((b*4 + q)*64 + blockIdx.y*8 + blockIdx.x)*64 + tid))*28;
    #pragma unroll
    for (int i = 0; i < 7; i++)
        *reinterpret_cast<float4*>(mp + 4*i) =
            make_float4(v[4*i], v[4*i+1], v[4*i+2], v[4*i+3]);
}

// ---------------------------------------------------------------------------
// K3: unchanged from R8.
// ---------------------------------------------------------------------------
#define XSTR 156
#define MP3 116

__global__ __launch_bounds__(128) void k3_reassemble(
    const float* __restrict__ x, float* __restrict__ out)
{
    __shared__ __align__(16) float s_mask[64*MP3];
    __shared__ __align__(16) float s_x[2][4*XSTR];

    const int tid  = threadIdx.x;
    const int px   = tid & 63;
    const int slot = tid >> 6;
    const int trow = px >> 3, tcol = px & 7;
    const int bz   = blockIdx.z;
    const int b    = bz >> 2;
    const int cbase = (bz & 3) * 64;
    const int col0 = blockIdx.x * 8, row0 = blockIdx.y * 8;
    const int gi = row0 + trow, gj = col0 + tcol;
    const int tileIdx = blockIdx.y*8 + blockIdx.x;

    #pragma unroll
    for (int qq = 0; qq < 4; qq++) {
        const float4* gm = reinterpret_cast<const float4*>(
            g_mask3 + (size_t)(((b*4 + qq)*64 + tileIdx)*64)*28);
        #pragma unroll
        for (int j = 0; j < 4; j++) {
            int i4 = tid + j*128;
            if (i4 < 448) {
                float4 v = gm[i4];
                int f = i4*4;
                int pxi = f / 28, t = f - pxi*28;
                float* d = &s_mask[pxi*MP3 + qq*29 + t];
                d[0] = v.x; d[1] = v.y; d[2] = v.z; d[3] = v.w;
            }
        }
    }

    const float* xb   = x   + (size_t)b*Cn*HW + (size_t)cbase*HW;
    float*       outb = out + (size_t)b*Cn*OH*OW;

    int  goff[5];
    int  soff[5];
    bool pred[5];
    #pragma unroll
    for (int i = 0; i < 5; i++) {
        int idx = tid + i*128;
        int cl = idx / 144, rr = idx - cl*144;
        int ly = rr / 12, lx = rr - ly*12;
        int gy = row0 - 2 + ly, gx = col0 - 2 + lx;
        bool inb = (idx < 576) && ((unsigned)gy < Hf) && ((unsigned)gx < Wf);
        pred[i] = inb;
        goff[i] = cl*HW + gy*Wf + gx;
        soff[i] = (idx < 576) ? (cl*XSTR + ly*13 + lx) : 0;
    }

    float pre[5];
    #define K3_LDG(it) { const float* _a = xb + (size_t)(it)*4*HW; \
        _Pragma("unroll") for (int i = 0; i < 5; i++) \
            pre[i] = pred[i] ? _a[goff[i]] : 0.f; }
    #define K3_STS(buf) { \
        _Pragma("unroll") for (int i = 0; i < 5; i++) \
            if (i < 4 || tid < 64) s_x[buf][soff[i]] = pre[i]; }

    K3_LDG(0);
    K3_STS(0);
    __syncthreads();

    u64t m01[25], m23[25];
    {
        const float* sm = &s_mask[px*MP3];
        #pragma unroll
        for (int k = 0; k < 25; k++) {
            m01[k] = pack2(sm[k],      sm[29 + k]);
            m23[k] = pack2(sm[58 + k], sm[87 + k]);
        }
    }

    #pragma unroll 1
    for (int it = 0; it < 16; it++) {
        const int cur = it & 1;
        if (it < 15) K3_LDG(it + 1);

        const float* p0 = &s_x[cur][(slot*2)*XSTR + trow*13 + tcol];
        u64t a01_0 = 0ULL, a23_0 = 0ULL, a01_1 = 0ULL, a23_1 = 0ULL;
        #pragma unroll
        for (int k = 0; k < 25; k++) {
            const int dy = k / 5, dx = k - dy*5;
            const int off = dy*13 + dx;
            u64t xx0 = dup2(p0[off]);
            u64t xx1 = dup2(p0[off + XSTR]);
            FMA2(a01_0, m01[k], xx0, a01_0);
            FMA2(a23_0, m23[k], xx0, a23_0);
            FMA2(a01_1, m01[k], xx1, a01_1);
            FMA2(a23_1, m23[k], xx1, a23_1);
        }

        const int c0 = cbase + it*4 + slot*2;
        float* op0 = outb + (size_t)c0*OH*OW;
        *reinterpret_cast<float2*>(op0 + (2*gi    )*OW + 2*gj) = unpk(a01_0);
        *reinterpret_cast<float2*>(op0 + (2*gi + 1)*OW + 2*gj) = unpk(a23_0);
        float* op1 = op0 + OH*OW;
        *reinterpret_cast<float2*>(op1 + (2*gi    )*OW + 2*gj) = unpk(a01_1);
        *reinterpret_cast<float2*>(op1 + (2*gi + 1)*OW + 2*gj) = unpk(a23_1);

        if (it < 15) K3_STS(cur ^ 1);
        __syncthreads();
    }
    #undef K3_LDG
    #undef K3_STS
}

// Dummy first launch: shifts the profiled slot (4th of each 4-launch group)
// onto k3 this round.
__global__ void k_phase() {}

// ---------------------------------------------------------------------------
extern "C" void kernel_launch(void* const* d_in, const int* in_sizes, int n_in,
                              void* d_out, int out_size)
{
    const float* x      = (const float*)d_in[0];
    const float* w_comp = (const float*)d_in[1];
    const float* gamma  = (const float*)d_in[2];
    const float* beta   = (const float*)d_in[3];
    const float* mean   = (const float*)d_in[4];
    const float* var    = (const float*)d_in[5];
    const float* w_enc  = (const float*)d_in[6];
    float* out = (float*)d_out;

    const int k2_smem = (64*9*TPAD + 2*K2_BUF) * (int)sizeof(float);  // ~68KB
    cudaFuncSetAttribute(k2_conv_softmax,
                         cudaFuncAttributeMaxDynamicSharedMemorySize, k2_smem);

    k_phase<<<1, 32>>>();
    k1_comp_bn_silu<<<dim3(Bn*8, 8), 256>>>(x, w_comp, gamma, beta, mean, var);
    k2_conv_softmax<<<dim3(8, 8, Bn*4), 64, k2_smem>>>(w_enc);
    k3_reassemble<<<dim3(8, 8, Bn*4), 128>>>(x, out);
}

// round 14
// speedup vs baseline: 1.3606x; 1.3606x over previous
#include <cuda_runtime.h>

#define Bn   4
#define Cn   256
#define Hf   64
#define Wf   64
#define HW   (Hf*Wf)
#define COMPn 64
#define OH   128
#define OW   128
#define EPSc 1e-5f
#define TPAD 28

typedef unsigned long long u64t;

#define FMA2(d, a, b, c) asm("fma.rn.f32x2 %0, %1, %2, %3;" : "=l"(d) : "l"(a), "l"(b), "l"(c))
#define ADD2(d, a, b)    asm("add.rn.f32x2 %0, %1, %2;"     : "=l"(d) : "l"(a), "l"(b))

__device__ __forceinline__ u64t dup2(float v) {
    u64t r; asm("mov.b64 %0, {%1, %1};" : "=l"(r) : "f"(v)); return r;
}
__device__ __forceinline__ float2 unpk(u64t v) {
    float lo, hi; asm("mov.b64 {%0, %1}, %2;" : "=f"(lo), "=f"(hi) : "l"(v));
    return make_float2(lo, hi);
}
__device__ __forceinline__ u64t pack2(float a, float b) {
    u64t r; asm("mov.b64 %0, {%1, %2};" : "=l"(r) : "f"(a), "f"(b)); return r;
}
__device__ __forceinline__ unsigned smem_u32(const void* p) {
    unsigned a;
    asm("{ .reg .u64 t; cvta.to.shared.u64 t, %1; cvt.u32.u64 %0, t; }" : "=r"(a) : "l"(p));
    return a;
}
__device__ __forceinline__ void cp_async4(unsigned dst, const void* src, int zf) {
    asm volatile("cp.async.ca.shared.global [%0], [%1], 4, %2;" :: "r"(dst), "l"(src), "r"(zf));
}
__device__ __forceinline__ void cp_commit() { asm volatile("cp.async.commit_group;"); }
__device__ __forceinline__ void cp_wait0()  { asm volatile("cp.async.wait_group 0;"); }

__device__ float g_act[Bn*COMPn*HW];
// masks q-major: [b][q][tileY*8+tileX][pixInTile(64)][28]
__device__ float g_mask3[Bn*4*64*64*28];

// ---------------------------------------------------------------------------
// K1: unchanged (27 us).
// ---------------------------------------------------------------------------
__global__ __launch_bounds__(256) void k1_comp_bn_silu(
    const float* __restrict__ x, const float* __restrict__ w_comp,
    const float* __restrict__ gamma, const float* __restrict__ beta,
    const float* __restrict__ mean, const float* __restrict__ var)
{
    __shared__ __align__(16) float sw[8*256*2];
    __shared__ __align__(16) u64t red[128][2][4][2];

    const int tid     = threadIdx.x;
    const int h       = tid >> 7;
    const int ht      = tid & 127;
    const int b       = blockIdx.x >> 3;
    const int pixBase = (blockIdx.x & 7) << 9;
    const int oBase   = blockIdx.y << 3;

    for (int i = tid; i < 8*256; i += 256) {
        int o = i >> 8, c = i & 255;
        float w = w_comp[(oBase + o)*256 + c];
        sw[2*i] = w; sw[2*i+1] = w;
    }
    __syncthreads();

    const int pix0 = pixBase + 4*ht;
    const float* xb = x + (size_t)b*Cn*HW + (size_t)(h*128)*HW + pix0;

    u64t acc[8][2];
    #pragma unroll
    for (int o = 0; o < 8; o++) { acc[o][0] = 0ULL; acc[o][1] = 0ULL; }

    const ulonglong2* sw2 = reinterpret_cast<const ulonglong2*>(sw);
    const int c4Base = h*32;

    ulonglong2 buf[2][4];
    #define LD4(s, g) { const float* _p = xb + (size_t)(g)*4*HW; \
        buf[s][0] = *(const ulonglong2*)(_p); \
        buf[s][1] = *(const ulonglong2*)(_p + HW); \
        buf[s][2] = *(const ulonglong2*)(_p + 2*HW); \
        buf[s][3] = *(const ulonglong2*)(_p + 3*HW); }
    #define K1STEP(s, g) { const int _gc = c4Base + (g); \
        _Pragma("unroll") for (int o = 0; o < 8; o++) { \
            ulonglong2 wA = sw2[o*128 + _gc*2]; \
            ulonglong2 wB = sw2[o*128 + _gc*2 + 1]; \
            FMA2(acc[o][0], wA.x, buf[s][0].x, acc[o][0]); \
            FMA2(acc[o][1], wA.x, buf[s][0].y, acc[o][1]); \
            FMA2(acc[o][0], wA.y, buf[s][1].x, acc[o][0]); \
            FMA2(acc[o][1], wA.y, buf[s][1].y, acc[o][1]); \
            FMA2(acc[o][0], wB.x, buf[s][2].x, acc[o][0]); \
            FMA2(acc[o][1], wB.x, buf[s][2].y, acc[o][1]); \
            FMA2(acc[o][0], wB.y, buf[s][3].x, acc[o][0]); \
            FMA2(acc[o][1], wB.y, buf[s][3].y, acc[o][1]); } }

    LD4(0, 0); LD4(1, 1);
    #pragma unroll 1
    for (int g = 0; g < 32; g += 2) {
        K1STEP(0, g);     if (g + 2 < 32) LD4(0, g + 2);
        K1STEP(1, g + 1); if (g + 3 < 32) LD4(1, g + 3);
    }
    #undef LD4
    #undef K1STEP

    #pragma unroll
    for (int j = 0; j < 4; j++) {
        red[ht][1 ^ h][j][0] = acc[(1 ^ h)*4 + j][0];
        red[ht][1 ^ h][j][1] = acc[(1 ^ h)*4 + j][1];
    }
    __syncthreads();

    #pragma unroll
    for (int j = 0; j < 4; j++) {
        int og = oBase + h*4 + j;
        u64t a0 = acc[h*4 + j][0], a1 = acc[h*4 + j][1];
        ADD2(a0, a0, red[ht][h][j][0]);
        ADD2(a1, a1, red[ht][h][j][1]);
        float inv = gamma[og] * rsqrtf(var[og] + EPSc);
        float mu = mean[og], bt = beta[og];
        float2 p0 = unpk(a0), p1 = unpk(a1);
        float v0 = (p0.x - mu)*inv + bt;
        float v1 = (p0.y - mu)*inv + bt;
        float v2 = (p1.x - mu)*inv + bt;
        float v3 = (p1.y - mu)*inv + bt;
        v0 = v0 / (1.f + __expf(-v0));
        v1 = v1 / (1.f + __expf(-v1));
        v2 = v2 / (1.f + __expf(-v2));
        v3 = v3 / (1.f + __expf(-v3));
        *reinterpret_cast<float4*>(&g_act[((size_t)b*COMPn + og)*HW + pix0]) =
            make_float4(v0, v1, v2, v3);
    }
}

// ---------------------------------------------------------------------------
// K2: R8 design (known-good): 16x16 tile, 2px/thr, 128 thr, grid (4,4,16),
// weights staged once (63KB, t-padded), acts double-buffered.
// ---------------------------------------------------------------------------
#define K2PCH 342
#define K2_BUF (4*K2PCH)

__global__ __launch_bounds__(128) void k2_conv_softmax(const float* __restrict__ w_enc)
{
    extern __shared__ __align__(16) float smem[];
    float* s_w   = smem;
    float* s_act = smem + 64*9*TPAD;

    const int tid   = threadIdx.x;
    const int trow  = tid >> 3;
    const int tcol0 = (tid & 7) << 1;
    const int bz    = blockIdx.z;
    const int b     = bz >> 2;
    const int q     = bz & 3;
    const int row0  = blockIdx.y * 16, col0 = blockIdx.x * 16;

    const float* actb = g_act + (size_t)b*COMPn*HW;

    int  goff[11];
    int  soff[11];
    bool pred[11];
    #pragma unroll
    for (int i = 0; i < 11; i++) {
        int idx = tid + i*128;
        int cl = idx / 324, r = idx - cl*324;
        int ly = r / 18,    lx = r - ly*18;
        int gy = row0 - 1 + ly, gx = col0 - 1 + lx;
        bool inb = (idx < 1296) && ((unsigned)gy < Hf) && ((unsigned)gx < Wf);
        pred[i] = inb;
        goff[i] = cl*HW + gy*Wf + gx;
        soff[i] = (idx < 1296) ? (cl*K2PCH + ly*19 + lx) : 0;
    }

    float pre[11];
    #define K2_LDG(chunk) { const float* _a = actb + (size_t)(chunk)*4*HW; \
        _Pragma("unroll") for (int i = 0; i < 11; i++) \
            pre[i] = pred[i] ? _a[goff[i]] : 0.f; }
    #define K2_STS(buf) { float* _d = s_act + (buf)*K2_BUF; \
        _Pragma("unroll") for (int i = 0; i < 11; i++) \
            if (i < 10 || tid < 16) _d[soff[i]] = pre[i]; }

    K2_LDG(0);

    for (int i = tid; i < 576; i += 128) {
        s_w[i*TPAD + 25] = 0.f; s_w[i*TPAD + 26] = 0.f; s_w[i*TPAD + 27] = 0.f;
    }
    for (int idx = tid; idx < 25*576; idx += 128) {
        int t = idx / 576, cj = idx - t*576;
        s_w[cj*TPAD + t] = w_enc[(t*4 + q)*576 + cj];
    }

    K2_STS(0);
    __syncthreads();

    u64t acc[2][13];
    #pragma unroll
    for (int p = 0; p < 2; p++)
        #pragma unroll
        for (int i = 0; i < 13; i++) acc[p][i] = 0ULL;

    #pragma unroll 1
    for (int ch = 0; ch < 16; ch++) {
        if (ch < 15) K2_LDG(ch + 1);

        const float* abuf = s_act + (ch & 1)*K2_BUF;
        #pragma unroll 1
        for (int cl = 0; cl < 4; cl++) {
            const int c = ch*4 + cl;
            const float* ab = abuf + cl*K2PCH + trow*19 + tcol0;
            u64t ad[3][4];
            #pragma unroll
            for (int jy = 0; jy < 3; jy++)
                #pragma unroll
                for (int jx = 0; jx < 4; jx++)
                    ad[jy][jx] = dup2(ab[jy*19 + jx]);

            const float* wb = s_w + c*9*TPAD;
            #pragma unroll
            for (int jy = 0; jy < 3; jy++)
            #pragma unroll
            for (int jx = 0; jx < 3; jx++) {
                const float* wj = wb + (jy*3 + jx)*TPAD;
                const ulonglong2* w2 = reinterpret_cast<const ulonglong2*>(wj);
                ulonglong2 wA = w2[0], wB = w2[1], wC = w2[2];
                ulonglong2 wD = w2[3], wE = w2[4], wF = w2[5];
                u64t wG = *reinterpret_cast<const u64t*>(wj + 24);
                u64t a0 = ad[jy][jx], a1 = ad[jy][jx+1];
                FMA2(acc[0][0],  wA.x, a0, acc[0][0]);  FMA2(acc[1][0],  wA.x, a1, acc[1][0]);
                FMA2(acc[0][1],  wA.y, a0, acc[0][1]);  FMA2(acc[1][1],  wA.y, a1, acc[1][1]);
                FMA2(acc[0][2],  wB.x, a0, acc[0][2]);  FMA2(acc[1][2],  wB.x, a1, acc[1][2]);
                FMA2(acc[0][3],  wB.y, a0, acc[0][3]);  FMA2(acc[1][3],  wB.y, a1, acc[1][3]);
                FMA2(acc[0][4],  wC.x, a0, acc[0][4]);  FMA2(acc[1][4],  wC.x, a1, acc[1][4]);
                FMA2(acc[0][5],  wC.y, a0, acc[0][5]);  FMA2(acc[1][5],  wC.y, a1, acc[1][5]);
                FMA2(acc[0][6],  wD.x, a0, acc[0][6]);  FMA2(acc[1][6],  wD.x, a1, acc[1][6]);
                FMA2(acc[0][7],  wD.y, a0, acc[0][7]);  FMA2(acc[1][7],  wD.y, a1, acc[1][7]);
                FMA2(acc[0][8],  wE.x, a0, acc[0][8]);  FMA2(acc[1][8],  wE.x, a1, acc[1][8]);
                FMA2(acc[0][9],  wE.y, a0, acc[0][9]);  FMA2(acc[1][9],  wE.y, a1, acc[1][9]);
                FMA2(acc[0][10], wF.x, a0, acc[0][10]); FMA2(acc[1][10], wF.x, a1, acc[1][10]);
                FMA2(acc[0][11], wF.y, a0, acc[0][11]); FMA2(acc[1][11], wF.y, a1, acc[1][11]);
                FMA2(acc[0][12], wG,   a0, acc[0][12]); FMA2(acc[1][12], wG,   a1, acc[1][12]);
            }
        }

        if (ch < 15) K2_STS((ch + 1) & 1);
        __syncthreads();
    }
    #undef K2_LDG
    #undef K2_STS

    const int gi = row0 + trow;
    #pragma unroll
    for (int p = 0; p < 2; p++) {
        float v[28];
        #pragma unroll
        for (int i = 0; i < 13; i++) {
            float2 u = unpk(acc[p][i]);
            v[2*i] = u.x; v[2*i+1] = u.y;
        }
        float mx = v[0];
        #pragma unroll
        for (int t = 1; t < 25; t++) mx = fmaxf(mx, v[t]);
        float sum = 0.f;
        #pragma unroll
        for (int t = 0; t < 25; t++) { v[t] = __expf(v[t] - mx); sum += v[t]; }
        float r = 1.f / sum;
        #pragma unroll
        for (int t = 0; t < 25; t++) v[t] *= r;
        v[25] = 0.f; v[26] = 0.f; v[27] = 0.f;

        const int gj = col0 + tcol0 + p;
        const int tY = gi >> 3, tX = gj >> 3;
        const int pit = ((gi & 7) << 3) | (gj & 7);
        float* mp = g_mask3 + ((size_t)(((b*4 + q)*64 + tY*8 + tX)*64 + pit))*28;
        #pragma unroll
        for (int i = 0; i < 7; i++)
            *reinterpret_cast<float4*>(mp + 4*i) =
                make_float4(v[4*i], v[4*i+1], v[4*i+2], v[4*i+3]);
    }
}

// ---------------------------------------------------------------------------
// K3 v2 FIXED: added the missing __syncthreads() between mask staging (STS)
// and mask packing (LDS) — R10's race. Flat conflict-free s_x, sign-encoded
// predicates, cp.async zfill staging. grid (8,8,16) x 128 thr, 4 CTAs/SM.
// ---------------------------------------------------------------------------
#define MP3 116

__global__ __launch_bounds__(128, 4) void k3_reassemble(
    const float* __restrict__ x, float* __restrict__ out)
{
    __shared__ __align__(16) float s_mask[64*MP3];
    __shared__ __align__(16) float s_x[2][576];

    const int tid  = threadIdx.x;
    const int px   = tid & 63;
    const int slot = tid >> 6;
    const int trow = px >> 3, tcol = px & 7;
    const int bz   = blockIdx.z;
    const int b    = bz >> 2;
    const int cbase = (bz & 3) * 64;
    const int col0 = blockIdx.x * 8, row0 = blockIdx.y * 8;
    const int gi = row0 + trow, gj = col0 + tcol;
    const int tileIdx = blockIdx.y*8 + blockIdx.x;

    // stage masks (q-major planes -> per-px [q][29] layout)
    #pragma unroll
    for (int qq = 0; qq < 4; qq++) {
        const float4* gm = reinterpret_cast<const float4*>(
            g_mask3 + (size_t)(((b*4 + qq)*64 + tileIdx)*64)*28);
        #pragma unroll
        for (int j = 0; j < 4; j++) {
            int i4 = tid + j*128;
            if (i4 < 448) {
                float4 v = gm[i4];
                int f = i4*4;
                int pxi = f / 28, t = f - pxi*28;
                float* d = &s_mask[pxi*MP3 + qq*29 + t];
                d[0] = v.x; d[1] = v.y; d[2] = v.z; d[3] = v.w;
            }
        }
    }

    const float* xb = x + (size_t)b*Cn*HW + (size_t)cbase*HW;
    float*      outb = out + (size_t)b*Cn*OH*OW;

    // staging offsets, predicate folded into sign
    int goff[5];
    #pragma unroll
    for (int i = 0; i < 5; i++) {
        int idx = tid + i*128;
        int cl = idx / 144, rr = idx - cl*144;
        int ly = rr / 12, lx = rr - ly*12;
        int gy = row0 - 2 + ly, gx = col0 - 2 + lx;
        bool ok = (idx < 576) && ((unsigned)gy < Hf) && ((unsigned)gx < Wf);
        goff[i] = ok ? (cl*HW + gy*Wf + gx) : -1;
    }
    const unsigned sx0 = smem_u32(&s_x[0][0]) + tid*4;

    #define K3_LDG(it, buf) { const float* _a = xb + (size_t)(it)*4*HW; \
        const unsigned _d = sx0 + (buf)*2304; \
        _Pragma("unroll") for (int i = 0; i < 4; i++) { \
            int _o = goff[i]; bool _ok = _o >= 0; \
            cp_async4(_d + i*512, _a + (_ok ? _o : 0), _ok ? 4 : 0); } \
        if (tid < 64) { int _o = goff[4]; bool _ok = _o >= 0; \
            cp_async4(_d + 4*512, _a + (_ok ? _o : 0), _ok ? 4 : 0); } \
        cp_commit(); }

    K3_LDG(0, 0);

    // FIX: order mask STS (above) before mask LDS (below) across the block.
    __syncthreads();

    // masks -> 50 packed regs
    u64t m01[25], m23[25];
    {
        const float* sm = &s_mask[px*MP3];
        #pragma unroll
        for (int k = 0; k < 25; k++) {
            m01[k] = pack2(sm[k],      sm[29 + k]);
            m23[k] = pack2(sm[58 + k], sm[87 + k]);
        }
    }

    cp_wait0();
    __syncthreads();

    #pragma unroll 1
    for (int it = 0; it < 16; it++) {
        const int cur = it & 1;
        if (it < 15) K3_LDG(it + 1, cur ^ 1);

        const float* p0 = &s_x[cur][slot*288 + trow*12 + tcol];
        u64t a01_0 = 0ULL, a23_0 = 0ULL, a01_1 = 0ULL, a23_1 = 0ULL;
        #pragma unroll
        for (int k = 0; k < 25; k++) {
            const int dy = k / 5, dx = k - dy*5;
            const int off = dy*12 + dx;
            u64t xx0 = dup2(p0[off]);
            u64t xx1 = dup2(p0[off + 144]);
            FMA2(a01_0, m01[k], xx0, a01_0);
            FMA2(a23_0, m23[k], xx0, a23_0);
            FMA2(a01_1, m01[k], xx1, a01_1);
            FMA2(a23_1, m23[k], xx1, a23_1);
        }

        const int c0 = cbase + it*4 + slot*2;
        float* op0 = outb + (size_t)c0*OH*OW;
        *reinterpret_cast<float2*>(op0 + (2*gi    )*OW + 2*gj) = unpk(a01_0);
        *reinterpret_cast<float2*>(op0 + (2*gi + 1)*OW + 2*gj) = unpk(a23_0);
        float* op1 = op0 + OH*OW;
        *reinterpret_cast<float2*>(op1 + (2*gi    )*OW + 2*gj) = unpk(a01_1);
        *reinterpret_cast<float2*>(op1 + (2*gi + 1)*OW + 2*gj) = unpk(a23_1);

        cp_wait0();
        __syncthreads();
    }
    #undef K3_LDG
}

// Phase shims: put k2 at 0-based launch index 3 (the slot ncu captures).
__global__ void k_phase() {}

// ---------------------------------------------------------------------------
extern "C" void kernel_launch(void* const* d_in, const int* in_sizes, int n_in,
                              void* d_out, int out_size)
{
    const float* x      = (const float*)d_in[0];
    const float* w_comp = (const float*)d_in[1];
    const float* gamma  = (const float*)d_in[2];
    const float* beta   = (const float*)d_in[3];
    const float* mean   = (const float*)d_in[4];
    const float* var    = (const float*)d_in[5];
    const float* w_enc  = (const float*)d_in[6];
    float* out = (float*)d_out;

    const int k2_smem = (64*9*TPAD + 2*K2_BUF) * (int)sizeof(float);  // ~74KB
    cudaFuncSetAttribute(k2_conv_softmax,
                         cudaFuncAttributeMaxDynamicSharedMemorySize, k2_smem);

    k1_comp_bn_silu<<<dim3(Bn*8, 8), 256>>>(x, w_comp, gamma, beta, mean, var);
    k_phase<<<1, 32>>>();
    k_phase<<<1, 32>>>();
    k2_conv_softmax<<<dim3(4, 4, Bn*4), 128, k2_smem>>>(w_enc);
    k3_reassemble<<<dim3(8, 8, Bn*4), 128>>>(x, out);
}